// round 15
// baseline (speedup 1.0000x reference)
#include <cuda_runtime.h>
#include <math.h>

// Problem constants
#define Bz 2
#define Tz 8
#define Cz 16
#define Hz 64
#define Wz 64
#define WFz 33
#define Dz 32
#define HIDz 128
#define HWz 4096
#define NIMG 256              // B*T*C
#define NIMG2 512             // 2B*T*C
#define UPLANE (Hz*WFz)       // 2112
#define USTR_T (Cz*UPLANE)    // 33792
#define NFIELD (Bz*Tz*Cz*HWz) // 1048576
#define NU (2*Bz*Tz*Cz*UPLANE)// 1081344

// Scratch (static __device__ — no allocation)
__device__ float g_xr[NFIELD];
__device__ float g_xi[NFIELD];
__device__ float g_ur[NU];
__device__ float g_ui[NU];
__device__ float g_Are[Cz], g_Aim[Cz];
__device__ float g_dts, g_nscale;

__device__ __forceinline__ float softplusf(float x) {
    return fmaxf(x, 0.f) + log1pf(expf(-fabsf(x)));
}

// ---------------------------------------------------------------- k_prep
__global__ void k_prep(const float* __restrict__ dt, const float* __restrict__ lam_re,
                       const float* __restrict__ lam_im, const float* __restrict__ dt_param,
                       const float* __restrict__ sigma) {
    int c = threadIdx.x;
    float dte = 0.f;
    if (c < Cz) {
        dte = dt[0] * softplusf(dt_param[c]);
        float are = -softplusf(lam_re[c]) * dte;
        float aim = lam_im[c] * dte;
        float m = expf(are);
        g_Are[c] = m * cosf(aim);
        g_Aim[c] = m * sinf(aim);
    }
    float s = dte;
#pragma unroll
    for (int o = 16; o > 0; o >>= 1) s += __shfl_xor_sync(0xffffffffu, s, o);
    if (c == 0) {
        float dts = s / 16.f;
        g_dts = dts;
        g_nscale = sigma[0] * sqrtf(dts);
    }
}

// ---------------------------------------------------------------- k_conv
// x1 = x + conv3x3(x) + b, applied to real and imag parts.
// block: (frame 0..15, part 0..1, cout 0..15) -> 512 blocks, 256 threads
__global__ void k_conv(const float* __restrict__ xr, const float* __restrict__ xi,
                       const float* __restrict__ conv_w, const float* __restrict__ conv_b) {
    __shared__ float sp[66][66];
    int bidx = blockIdx.x;
    int co   = bidx & 15;
    int part = (bidx >> 4) & 1;
    int f    = bidx >> 5;
    const float* src = part ? xi : xr;
    float*       dst = part ? g_xi : g_xr;
    int t = threadIdx.x;

    for (int i = t; i < 66 * 66; i += 256) ((float*)sp)[i] = 0.f;
    __syncthreads();

    float acc[16];
#pragma unroll
    for (int i = 0; i < 16; i++) acc[i] = 0.f;

    for (int ci = 0; ci < Cz; ci++) {
        const float* p = src + (f * Cz + ci) * HWz;
        for (int idx = t; idx < HWz; idx += 256)
            sp[(idx >> 6) + 1][(idx & 63) + 1] = p[idx];
        __syncthreads();
        const float* w = conv_w + (co * Cz + ci) * 9;
        float w0 = w[0], w1 = w[1], w2 = w[2], w3 = w[3], w4 = w[4],
              w5 = w[5], w6 = w[6], w7 = w[7], w8 = w[8];
#pragma unroll
        for (int i = 0; i < 16; i++) {
            int idx = t + 256 * i;
            int y = (idx >> 6) + 1, x = (idx & 63) + 1;
            float a = acc[i];
            a = fmaf(w0, sp[y - 1][x - 1], a);
            a = fmaf(w1, sp[y - 1][x    ], a);
            a = fmaf(w2, sp[y - 1][x + 1], a);
            a = fmaf(w3, sp[y    ][x - 1], a);
            a = fmaf(w4, sp[y    ][x    ], a);
            a = fmaf(w5, sp[y    ][x + 1], a);
            a = fmaf(w6, sp[y + 1][x - 1], a);
            a = fmaf(w7, sp[y + 1][x    ], a);
            a = fmaf(w8, sp[y + 1][x + 1], a);
            acc[i] = a;
        }
        __syncthreads();
    }
    const float* me = src + (f * Cz + co) * HWz;
    float*       de = dst + (f * Cz + co) * HWz;
    float bb = conv_b[co];
#pragma unroll
    for (int i = 0; i < 16; i++) {
        int idx = t + 256 * i;
        de[idx] = me[idx] + acc[i] + bb;
    }
}

// ---------------------------------------------------------------- DFT passes
// 64-pt DFT along H (columns) and W (rows), in-place via register double-buffer.
// sgn = -1 forward (e^{-i}), +1 inverse (e^{+i}); each pass scales by 1/8 (ortho).
__device__ void dft_h(float (*ar)[65], float (*ai)[65],
                      const float* __restrict__ tc, const float* __restrict__ ts, float sgn) {
    int t = threadIdx.x;
    int cx = t & 63, kb = t >> 6;
    float orr[16], ori[16];
#pragma unroll
    for (int i = 0; i < 16; i++) { orr[i] = 0.f; ori[i] = 0.f; }
    for (int r = 0; r < 64; r++) {
        float x = ar[r][cx], y = ai[r][cx];
        float xs = sgn * x, ym = -sgn * y;
        int m = (kb * r) & 63, st = (r << 2) & 63;
#pragma unroll
        for (int i = 0; i < 16; i++) {
            float c = tc[m], s = ts[m];
            orr[i] = fmaf(x, c, fmaf(ym, s, orr[i]));
            ori[i] = fmaf(y, c, fmaf(xs, s, ori[i]));
            m = (m + st) & 63;
        }
    }
    __syncthreads();
#pragma unroll
    for (int i = 0; i < 16; i++) {
        int k = kb + 4 * i;
        ar[k][cx] = orr[i] * 0.125f;
        ai[k][cx] = ori[i] * 0.125f;
    }
    __syncthreads();
}

__device__ void dft_w(float (*ar)[65], float (*ai)[65],
                      const float* __restrict__ tc, const float* __restrict__ ts, float sgn) {
    int t = threadIdx.x;
    int r = t & 63, kb = t >> 6;
    float orr[16], ori[16];
#pragma unroll
    for (int i = 0; i < 16; i++) { orr[i] = 0.f; ori[i] = 0.f; }
    for (int n = 0; n < 64; n++) {
        float x = ar[r][n], y = ai[r][n];
        float xs = sgn * x, ym = -sgn * y;
        int m = (kb * n) & 63, st = (n << 2) & 63;
#pragma unroll
        for (int i = 0; i < 16; i++) {
            float c = tc[m], s = ts[m];
            orr[i] = fmaf(x, c, fmaf(ym, s, orr[i]));
            ori[i] = fmaf(y, c, fmaf(xs, s, ori[i]));
            m = (m + st) & 63;
        }
    }
    __syncthreads();
#pragma unroll
    for (int i = 0; i < 16; i++) {
        int k = kb + 4 * i;
        ar[r][k] = orr[i] * 0.125f;
        ai[r][k] = ori[i] * 0.125f;
    }
    __syncthreads();
}

#define FFT_SHARED                                                        \
    __shared__ float sar[64][65];                                         \
    __shared__ float sai[64][65];                                         \
    __shared__ float stc[64], sts[64];                                    \
    {                                                                     \
        int t_ = threadIdx.x;                                             \
        if (t_ < 64) {                                                    \
            float th = 0.09817477042468103f * (float)t_;                  \
            stc[t_] = cosf(th);                                           \
            sts[t_] = sinf(th);                                           \
        }                                                                 \
    }

// ---------------------------------------------------------------- k_spectral
// x += ifft2( fft2(x) * filt ), per (b,t,c) image. 256 blocks.
__global__ void k_spectral(const float* __restrict__ spec_re, const float* __restrict__ spec_im) {
    FFT_SHARED
    int img = blockIdx.x;
    int c = img & 15;
    int base = img * HWz;
    int t = threadIdx.x;
    for (int idx = t; idx < HWz; idx += 256) {
        int hh = idx >> 6, ww = idx & 63;
        sar[hh][ww] = g_xr[base + idx];
        sai[hh][ww] = g_xi[base + idx];
    }
    __syncthreads();
    dft_h(sar, sai, stc, sts, -1.f);
    dft_w(sar, sai, stc, sts, -1.f);
    for (int idx = t; idx < HWz; idx += 256) {
        int hh = idx >> 6, ww = idx & 63;
        float fr = spec_re[c * HWz + idx], fi = spec_im[c * HWz + idx];
        float x = sar[hh][ww], y = sai[hh][ww];
        sar[hh][ww] = x * fr - y * fi;
        sai[hh][ww] = x * fi + y * fr;
    }
    __syncthreads();
    dft_h(sar, sai, stc, sts, 1.f);
    dft_w(sar, sai, stc, sts, 1.f);
    for (int idx = t; idx < HWz; idx += 256) {
        int hh = idx >> 6, ww = idx & 63;
        g_xr[base + idx] += sar[hh][ww];
        g_xi[base + idx] += sai[hh][ww];
    }
}

// ---------------------------------------------------------------- k_rfft2
// u = rfft2(xs) for xs = [x.real ; x.imag] (bb = 0..3). 512 blocks.
__global__ void k_rfft2() {
    FFT_SHARED
    int img = blockIdx.x;
    int bb = img / (Tz * Cz);
    int rem = img % (Tz * Cz);
    const float* src = (bb < 2) ? g_xr : g_xi;
    int base = ((bb & 1) * Tz * Cz + rem) * HWz;
    int t = threadIdx.x;
    for (int idx = t; idx < HWz; idx += 256) {
        int hh = idx >> 6, ww = idx & 63;
        sar[hh][ww] = src[base + idx];
        sai[hh][ww] = 0.f;
    }
    __syncthreads();
    dft_h(sar, sai, stc, sts, -1.f);
    dft_w(sar, sai, stc, sts, -1.f);
    int ub = img * UPLANE;
    for (int idx = t; idx < UPLANE; idx += 256) {
        int hh = idx / 33, ww = idx % 33;
        g_ur[ub + idx] = sar[hh][ww];
        g_ui[ub + idx] = sai[hh][ww];
    }
}

// ---------------------------------------------------------------- k_scan
// h_t = A[c] h_{t-1} + u_t  (in-place over u), per frequency bin.
__global__ void k_scan() {
    int idx = blockIdx.x * blockDim.x + threadIdx.x;
    if (idx >= 4 * USTR_T) return;
    int bb = idx / USTR_T;
    int inner = idx % USTR_T;
    int c = inner / UPLANE;
    float Ar = g_Are[c], Ai = g_Aim[c];
    int base = bb * (Tz * USTR_T) + inner;
    float hr = 0.f, hi = 0.f;
#pragma unroll
    for (int tt = 0; tt < Tz; tt++) {
        int o = base + tt * USTR_T;
        float ur = g_ur[o], ui = g_ui[o];
        float nr = Ar * hr - Ai * hi + ur;
        float ni = Ar * hi + Ai * hr + ui;
        hr = nr; hi = ni;
        g_ur[o] = hr; g_ui[o] = hi;
    }
}

// ---------------------------------------------------------------- k_irfft2
// x += irfft2(h) + noise*scale.  Hermitian-extend half spectrum, ifft2, Re part.
__global__ void k_irfft2(const float* __restrict__ noise_r, const float* __restrict__ noise_i) {
    FFT_SHARED
    int img = blockIdx.x;
    int bb = img / (Tz * Cz);
    int rem = img % (Tz * Cz);
    int ub = img * UPLANE;
    int t = threadIdx.x;
    for (int idx = t; idx < HWz; idx += 256) {
        int hh = idx >> 6, ww = idx & 63;
        float re, im;
        if (ww < WFz) {
            re = g_ur[ub + hh * 33 + ww];
            im = g_ui[ub + hh * 33 + ww];
        } else {
            int hs = (64 - hh) & 63;
            int ws = 64 - ww;
            re =  g_ur[ub + hs * 33 + ws];
            im = -g_ui[ub + hs * 33 + ws];
        }
        sar[hh][ww] = re;
        sai[hh][ww] = im;
    }
    __syncthreads();
    dft_h(sar, sai, stc, sts, 1.f);
    dft_w(sar, sai, stc, sts, 1.f);
    float ns = g_nscale;
    int base = ((bb & 1) * Tz * Cz + rem) * HWz;
    float* dst = (bb < 2) ? g_xr : g_xi;
    const float* nz = (bb < 2) ? noise_r : noise_i;
    for (int idx = t; idx < HWz; idx += 256) {
        int hh = idx >> 6, ww = idx & 63;
        dst[base + idx] += sar[hh][ww] + ns * nz[base + idx];
    }
}

// ---------------------------------------------------------------- k_ph
// Port-Hamiltonian layer. Block = one (b,t,h) row of 64 positions. 1024 blocks.
__global__ void __launch_bounds__(256) k_ph(
    const float* __restrict__ ln_g, const float* __restrict__ ln_b,
    const float* __restrict__ W1, const float* __restrict__ b1,
    const float* __restrict__ w2,
    const float* __restrict__ JgW, const float* __restrict__ Jgb,
    const float* __restrict__ RgW, const float* __restrict__ Rgb,
    float* __restrict__ out) {
    __shared__ float sW1[32][129];
    __shared__ float sXc[64][33];
    __shared__ float sXin[64][33];
    __shared__ float sG[64][33];
    __shared__ float sWc[32][33];           // also aliased as coef buffer in phase 1
    float* sCoef = &sWc[0][0];              // 1056 floats >= 8*128

    int tdx = threadIdx.x;
    int bid = blockIdx.x;
    int f = bid >> 6;       // frame b*T+t
    int hh = bid & 63;

    for (int i = tdx; i < 32 * 128; i += 256) sW1[i >> 7][i & 127] = W1[i];
    for (int i = tdx; i < 1024; i += 256) {
        int c = i >> 6, w = i & 63;
        int gi = (f * Cz + c) * HWz + hh * 64 + w;
        sXc[w][c] = g_xr[gi];
        sXc[w][16 + c] = g_xi[gi];
    }
    __syncthreads();

    int lane = tdx & 31, pg = tdx >> 5;
    float dts = g_dts;
    float lng = ln_g[lane], lnb = ln_b[lane];
    float b1r[4], w2r[4];
#pragma unroll
    for (int k4 = 0; k4 < 4; k4++) { b1r[k4] = b1[lane + 32 * k4]; w2r[k4] = w2[lane + 32 * k4]; }

    // phase 1: layernorm + MLP potential gradient
    for (int pp = 0; pp < 8; pp++) {
        int pos = pg * 8 + pp;
        float v = sXc[pos][lane];
        float s1 = v, s2 = v * v;
#pragma unroll
        for (int o = 16; o > 0; o >>= 1) {
            s1 += __shfl_xor_sync(0xffffffffu, s1, o);
            s2 += __shfl_xor_sync(0xffffffffu, s2, o);
        }
        float mu = s1 * (1.f / 32.f);
        float var = s2 * (1.f / 32.f) - mu * mu;
        float xin = (v - mu) * rsqrtf(var + 1e-5f) * lng + lnb;
        sXin[pos][lane] = xin;
        __syncwarp();
#pragma unroll
        for (int k4 = 0; k4 < 4; k4++) {
            int jj = lane + 32 * k4;
            float s = b1r[k4];
#pragma unroll
            for (int i = 0; i < 32; i++) s = fmaf(sXin[pos][i], sW1[i][jj], s);
            float sg = 1.f / (1.f + expf(-s));
            sCoef[pg * 128 + jj] = w2r[k4] * sg * (1.f + s * (1.f - sg));
        }
        __syncwarp();
        float gg = 0.f;
#pragma unroll 8
        for (int jj = 0; jj < 128; jj++) gg = fmaf(sW1[lane][jj], sCoef[pg * 128 + jj], gg);
        sG[pos][lane] = gg;
        __syncwarp();
    }
    __syncthreads();

    // phase 2: single pass over M/P rows k: Mg (lane j==k), M^T g, P^T P g
    float rMg[8], rMT[8], rU[8];
#pragma unroll
    for (int i = 0; i < 8; i++) { rMg[i] = 0.f; rMT[i] = 0.f; rU[i] = 0.f; }
    int j = lane;
    for (int k = 0; k < 32; k++) {
        for (int l = tdx; l < 1024; l += 256)
            sWc[l >> 5][l & 31] = JgW[(l >> 5) * 1024 + k * 32 + (l & 31)];
        __syncthreads();
        float bia = Jgb[k * 32 + j];
#pragma unroll
        for (int pp = 0; pp < 8; pp++) {
            int pos = pg * 8 + pp;
            float m = bia;
#pragma unroll
            for (int a = 0; a < 32; a++) m = fmaf(sXin[pos][a], sWc[a][j], m);
            float red = m * sG[pos][j];
#pragma unroll
            for (int o = 16; o > 0; o >>= 1) red += __shfl_xor_sync(0xffffffffu, red, o);
            if (j == k) rMg[pp] = red;
            rMT[pp] = fmaf(m, sG[pos][k], rMT[pp]);
        }
        __syncthreads();
        for (int l = tdx; l < 1024; l += 256)
            sWc[l >> 5][l & 31] = RgW[(l >> 5) * 1024 + k * 32 + (l & 31)];
        __syncthreads();
        float bib = Rgb[k * 32 + j];
#pragma unroll
        for (int pp = 0; pp < 8; pp++) {
            int pos = pg * 8 + pp;
            float p = bib;
#pragma unroll
            for (int a = 0; a < 32; a++) p = fmaf(sXin[pos][a], sWc[a][j], p);
            float q = p * sG[pos][j];
#pragma unroll
            for (int o = 16; o > 0; o >>= 1) q += __shfl_xor_sync(0xffffffffu, q, o);
            rU[pp] = fmaf(p, q, rU[pp]);
        }
        __syncthreads();
    }

    // finalize: out = xc + dt_scalar * (Mg - M^T g - P^T P g - 1e-4 g)
#pragma unroll
    for (int pp = 0; pp < 8; pp++) {
        int pos = pg * 8 + pp;
        float upd = rMg[pp] - rMT[pp] - rU[pp] - 1e-4f * sG[pos][j];
        sXin[pos][j] = sXc[pos][j] + dts * upd;
    }
    __syncthreads();
    for (int i = tdx; i < 2048; i += 256) {
        int d = i >> 6, w = i & 63;
        out[((f * Dz + d) * Hz + hh) * Wz + w] = sXin[w][d];
    }
}

// ---------------------------------------------------------------- launch
extern "C" void kernel_launch(void* const* d_in, const int* in_sizes, int n_in,
                              void* d_out, int out_size) {
    const float* x_real   = (const float*)d_in[0];
    const float* x_imag   = (const float*)d_in[1];
    const float* dt       = (const float*)d_in[2];
    const float* conv_w   = (const float*)d_in[3];
    const float* conv_b   = (const float*)d_in[4];
    const float* spec_re  = (const float*)d_in[5];
    const float* spec_im  = (const float*)d_in[6];
    const float* lam_re   = (const float*)d_in[7];
    const float* lam_im   = (const float*)d_in[8];
    const float* dt_param = (const float*)d_in[9];
    const float* sigma    = (const float*)d_in[10];
    const float* noise_r  = (const float*)d_in[11];
    const float* noise_i  = (const float*)d_in[12];
    const float* ln_g     = (const float*)d_in[13];
    const float* ln_b     = (const float*)d_in[14];
    const float* W1       = (const float*)d_in[15];
    const float* b1       = (const float*)d_in[16];
    const float* w2       = (const float*)d_in[17];
    // d_in[18] = b2 (constant in potential; zero gradient -> unused)
    const float* JgW      = (const float*)d_in[19];
    const float* Jgb      = (const float*)d_in[20];
    const float* RgW      = (const float*)d_in[21];
    const float* Rgb      = (const float*)d_in[22];
    float* out = (float*)d_out;

    k_prep<<<1, 32>>>(dt, lam_re, lam_im, dt_param, sigma);
    k_conv<<<512, 256>>>(x_real, x_imag, conv_w, conv_b);
    k_spectral<<<256, 256>>>(spec_re, spec_im);
    k_rfft2<<<512, 256>>>();
    k_scan<<<528, 256>>>();
    k_irfft2<<<512, 256>>>(noise_r, noise_i);
    k_ph<<<1024, 256>>>(ln_g, ln_b, W1, b1, w2, JgW, Jgb, RgW, Rgb, out);
}

// round 16
// speedup vs baseline: 1.0015x; 1.0015x over previous
#include <cuda_runtime.h>
#include <math.h>

// Problem constants
#define Bz 2
#define Tz 8
#define Cz 16
#define Hz 64
#define Wz 64
#define WFz 33
#define Dz 32
#define HIDz 128
#define HWz 4096
#define NIMG 256              // B*T*C
#define NIMG2 512             // 2B*T*C
#define UPLANE (Hz*WFz)       // 2112
#define USTR_T (Cz*UPLANE)    // 33792
#define NFIELD (Bz*Tz*Cz*HWz) // 1048576
#define NU (2*Bz*Tz*Cz*UPLANE)// 1081344

// Scratch (static __device__ — no allocation)
__device__ float g_xr[NFIELD];
__device__ float g_xi[NFIELD];
__device__ float g_ur[NU];
__device__ float g_ui[NU];
__device__ float g_Are[Cz], g_Aim[Cz];
__device__ float g_dts, g_nscale;

__device__ __forceinline__ float softplusf(float x) {
    return fmaxf(x, 0.f) + log1pf(expf(-fabsf(x)));
}

// ---------------------------------------------------------------- k_prep
__global__ void k_prep(const float* __restrict__ dt, const float* __restrict__ lam_re,
                       const float* __restrict__ lam_im, const float* __restrict__ dt_param,
                       const float* __restrict__ sigma) {
    int c = threadIdx.x;
    float dte = 0.f;
    if (c < Cz) {
        dte = dt[0] * softplusf(dt_param[c]);
        float are = -softplusf(lam_re[c]) * dte;
        float aim = lam_im[c] * dte;
        float m = expf(are);
        g_Are[c] = m * cosf(aim);
        g_Aim[c] = m * sinf(aim);
    }
    float s = dte;
#pragma unroll
    for (int o = 16; o > 0; o >>= 1) s += __shfl_xor_sync(0xffffffffu, s, o);
    if (c == 0) {
        float dts = s / 16.f;
        g_dts = dts;
        g_nscale = sigma[0] * sqrtf(dts);
    }
}

// ---------------------------------------------------------------- k_conv
// x1 = x + conv3x3(x) + b, applied to real and imag parts.
// block: (frame 0..15, part 0..1, cout 0..15) -> 512 blocks, 256 threads
__global__ void k_conv(const float* __restrict__ xr, const float* __restrict__ xi,
                       const float* __restrict__ conv_w, const float* __restrict__ conv_b) {
    __shared__ float sp[66][66];
    int bidx = blockIdx.x;
    int co   = bidx & 15;
    int part = (bidx >> 4) & 1;
    int f    = bidx >> 5;
    const float* src = part ? xi : xr;
    float*       dst = part ? g_xi : g_xr;
    int t = threadIdx.x;

    for (int i = t; i < 66 * 66; i += 256) ((float*)sp)[i] = 0.f;
    __syncthreads();

    float acc[16];
#pragma unroll
    for (int i = 0; i < 16; i++) acc[i] = 0.f;

    for (int ci = 0; ci < Cz; ci++) {
        const float* p = src + (f * Cz + ci) * HWz;
        for (int idx = t; idx < HWz; idx += 256)
            sp[(idx >> 6) + 1][(idx & 63) + 1] = p[idx];
        __syncthreads();
        const float* w = conv_w + (co * Cz + ci) * 9;
        float w0 = w[0], w1 = w[1], w2 = w[2], w3 = w[3], w4 = w[4],
              w5 = w[5], w6 = w[6], w7 = w[7], w8 = w[8];
#pragma unroll
        for (int i = 0; i < 16; i++) {
            int idx = t + 256 * i;
            int y = (idx >> 6) + 1, x = (idx & 63) + 1;
            float a = acc[i];
            a = fmaf(w0, sp[y - 1][x - 1], a);
            a = fmaf(w1, sp[y - 1][x    ], a);
            a = fmaf(w2, sp[y - 1][x + 1], a);
            a = fmaf(w3, sp[y    ][x - 1], a);
            a = fmaf(w4, sp[y    ][x    ], a);
            a = fmaf(w5, sp[y    ][x + 1], a);
            a = fmaf(w6, sp[y + 1][x - 1], a);
            a = fmaf(w7, sp[y + 1][x    ], a);
            a = fmaf(w8, sp[y + 1][x + 1], a);
            acc[i] = a;
        }
        __syncthreads();
    }
    const float* me = src + (f * Cz + co) * HWz;
    float*       de = dst + (f * Cz + co) * HWz;
    float bb = conv_b[co];
#pragma unroll
    for (int i = 0; i < 16; i++) {
        int idx = t + 256 * i;
        de[idx] = me[idx] + acc[i] + bb;
    }
}

// ---------------------------------------------------------------- DFT passes
// 64-pt DFT along H (columns) and W (rows), in-place via register double-buffer.
// sgn = -1 forward (e^{-i}), +1 inverse (e^{+i}); each pass scales by 1/8 (ortho).
__device__ void dft_h(float (*ar)[65], float (*ai)[65],
                      const float* __restrict__ tc, const float* __restrict__ ts, float sgn) {
    int t = threadIdx.x;
    int cx = t & 63, kb = t >> 6;
    float orr[16], ori[16];
#pragma unroll
    for (int i = 0; i < 16; i++) { orr[i] = 0.f; ori[i] = 0.f; }
    for (int r = 0; r < 64; r++) {
        float x = ar[r][cx], y = ai[r][cx];
        float xs = sgn * x, ym = -sgn * y;
        int m = (kb * r) & 63, st = (r << 2) & 63;
#pragma unroll
        for (int i = 0; i < 16; i++) {
            float c = tc[m], s = ts[m];
            orr[i] = fmaf(x, c, fmaf(ym, s, orr[i]));
            ori[i] = fmaf(y, c, fmaf(xs, s, ori[i]));
            m = (m + st) & 63;
        }
    }
    __syncthreads();
#pragma unroll
    for (int i = 0; i < 16; i++) {
        int k = kb + 4 * i;
        ar[k][cx] = orr[i] * 0.125f;
        ai[k][cx] = ori[i] * 0.125f;
    }
    __syncthreads();
}

__device__ void dft_w(float (*ar)[65], float (*ai)[65],
                      const float* __restrict__ tc, const float* __restrict__ ts, float sgn) {
    int t = threadIdx.x;
    int r = t & 63, kb = t >> 6;
    float orr[16], ori[16];
#pragma unroll
    for (int i = 0; i < 16; i++) { orr[i] = 0.f; ori[i] = 0.f; }
    for (int n = 0; n < 64; n++) {
        float x = ar[r][n], y = ai[r][n];
        float xs = sgn * x, ym = -sgn * y;
        int m = (kb * n) & 63, st = (n << 2) & 63;
#pragma unroll
        for (int i = 0; i < 16; i++) {
            float c = tc[m], s = ts[m];
            orr[i] = fmaf(x, c, fmaf(ym, s, orr[i]));
            ori[i] = fmaf(y, c, fmaf(xs, s, ori[i]));
            m = (m + st) & 63;
        }
    }
    __syncthreads();
#pragma unroll
    for (int i = 0; i < 16; i++) {
        int k = kb + 4 * i;
        ar[r][k] = orr[i] * 0.125f;
        ai[r][k] = ori[i] * 0.125f;
    }
    __syncthreads();
}

#define FFT_SHARED                                                        \
    __shared__ float sar[64][65];                                         \
    __shared__ float sai[64][65];                                         \
    __shared__ float stc[64], sts[64];                                    \
    {                                                                     \
        int t_ = threadIdx.x;                                             \
        if (t_ < 64) {                                                    \
            float th = 0.09817477042468103f * (float)t_;                  \
            stc[t_] = cosf(th);                                           \
            sts[t_] = sinf(th);                                           \
        }                                                                 \
    }

// ---------------------------------------------------------------- k_spectral
// x += ifft2( fft2(x) * filt ), per (b,t,c) image. 256 blocks.
__global__ void k_spectral(const float* __restrict__ spec_re, const float* __restrict__ spec_im) {
    FFT_SHARED
    int img = blockIdx.x;
    int c = img & 15;
    int base = img * HWz;
    int t = threadIdx.x;
    for (int idx = t; idx < HWz; idx += 256) {
        int hh = idx >> 6, ww = idx & 63;
        sar[hh][ww] = g_xr[base + idx];
        sai[hh][ww] = g_xi[base + idx];
    }
    __syncthreads();
    dft_h(sar, sai, stc, sts, -1.f);
    dft_w(sar, sai, stc, sts, -1.f);
    for (int idx = t; idx < HWz; idx += 256) {
        int hh = idx >> 6, ww = idx & 63;
        float fr = spec_re[c * HWz + idx], fi = spec_im[c * HWz + idx];
        float x = sar[hh][ww], y = sai[hh][ww];
        sar[hh][ww] = x * fr - y * fi;
        sai[hh][ww] = x * fi + y * fr;
    }
    __syncthreads();
    dft_h(sar, sai, stc, sts, 1.f);
    dft_w(sar, sai, stc, sts, 1.f);
    for (int idx = t; idx < HWz; idx += 256) {
        int hh = idx >> 6, ww = idx & 63;
        g_xr[base + idx] += sar[hh][ww];
        g_xi[base + idx] += sai[hh][ww];
    }
}

// ---------------------------------------------------------------- k_rfft2
// u = rfft2(xs) for xs = [x.real ; x.imag] (bb = 0..3). 512 blocks.
__global__ void k_rfft2() {
    FFT_SHARED
    int img = blockIdx.x;
    int bb = img / (Tz * Cz);
    int rem = img % (Tz * Cz);
    const float* src = (bb < 2) ? g_xr : g_xi;
    int base = ((bb & 1) * Tz * Cz + rem) * HWz;
    int t = threadIdx.x;
    for (int idx = t; idx < HWz; idx += 256) {
        int hh = idx >> 6, ww = idx & 63;
        sar[hh][ww] = src[base + idx];
        sai[hh][ww] = 0.f;
    }
    __syncthreads();
    dft_h(sar, sai, stc, sts, -1.f);
    dft_w(sar, sai, stc, sts, -1.f);
    int ub = img * UPLANE;
    for (int idx = t; idx < UPLANE; idx += 256) {
        int hh = idx / 33, ww = idx % 33;
        g_ur[ub + idx] = sar[hh][ww];
        g_ui[ub + idx] = sai[hh][ww];
    }
}

// ---------------------------------------------------------------- k_scan
// h_t = A[c] h_{t-1} + u_t  (in-place over u), per frequency bin.
__global__ void k_scan() {
    int idx = blockIdx.x * blockDim.x + threadIdx.x;
    if (idx >= 4 * USTR_T) return;
    int bb = idx / USTR_T;
    int inner = idx % USTR_T;
    int c = inner / UPLANE;
    float Ar = g_Are[c], Ai = g_Aim[c];
    int base = bb * (Tz * USTR_T) + inner;
    float hr = 0.f, hi = 0.f;
#pragma unroll
    for (int tt = 0; tt < Tz; tt++) {
        int o = base + tt * USTR_T;
        float ur = g_ur[o], ui = g_ui[o];
        float nr = Ar * hr - Ai * hi + ur;
        float ni = Ar * hi + Ai * hr + ui;
        hr = nr; hi = ni;
        g_ur[o] = hr; g_ui[o] = hi;
    }
}

// ---------------------------------------------------------------- k_irfft2
// x += irfft2(h) + noise*scale.  Hermitian-extend half spectrum, ifft2, Re part.
__global__ void k_irfft2(const float* __restrict__ noise_r, const float* __restrict__ noise_i) {
    FFT_SHARED
    int img = blockIdx.x;
    int bb = img / (Tz * Cz);
    int rem = img % (Tz * Cz);
    int ub = img * UPLANE;
    int t = threadIdx.x;
    for (int idx = t; idx < HWz; idx += 256) {
        int hh = idx >> 6, ww = idx & 63;
        float re, im;
        if (ww < WFz) {
            re = g_ur[ub + hh * 33 + ww];
            im = g_ui[ub + hh * 33 + ww];
        } else {
            int hs = (64 - hh) & 63;
            int ws = 64 - ww;
            re =  g_ur[ub + hs * 33 + ws];
            im = -g_ui[ub + hs * 33 + ws];
        }
        sar[hh][ww] = re;
        sai[hh][ww] = im;
    }
    __syncthreads();
    dft_h(sar, sai, stc, sts, 1.f);
    dft_w(sar, sai, stc, sts, 1.f);
    float ns = g_nscale;
    int base = ((bb & 1) * Tz * Cz + rem) * HWz;
    float* dst = (bb < 2) ? g_xr : g_xi;
    const float* nz = (bb < 2) ? noise_r : noise_i;
    for (int idx = t; idx < HWz; idx += 256) {
        int hh = idx >> 6, ww = idx & 63;
        dst[base + idx] += sar[hh][ww] + ns * nz[base + idx];
    }
}

// ---------------------------------------------------------------- k_ph
// Port-Hamiltonian layer. Block = one (b,t,h) row of 64 positions. 1024 blocks.
__global__ void __launch_bounds__(256) k_ph(
    const float* __restrict__ ln_g, const float* __restrict__ ln_b,
    const float* __restrict__ W1, const float* __restrict__ b1,
    const float* __restrict__ w2,
    const float* __restrict__ JgW, const float* __restrict__ Jgb,
    const float* __restrict__ RgW, const float* __restrict__ Rgb,
    float* __restrict__ out) {
    __shared__ float sW1[32][129];
    __shared__ float sXc[64][33];
    __shared__ float sXin[64][33];
    __shared__ float sG[64][33];
    __shared__ float sWc[32][33];           // also aliased as coef buffer in phase 1
    float* sCoef = &sWc[0][0];              // 1056 floats >= 8*128

    int tdx = threadIdx.x;
    int bid = blockIdx.x;
    int f = bid >> 6;       // frame b*T+t
    int hh = bid & 63;

    for (int i = tdx; i < 32 * 128; i += 256) sW1[i >> 7][i & 127] = W1[i];
    for (int i = tdx; i < 1024; i += 256) {
        int c = i >> 6, w = i & 63;
        int gi = (f * Cz + c) * HWz + hh * 64 + w;
        sXc[w][c] = g_xr[gi];
        sXc[w][16 + c] = g_xi[gi];
    }
    __syncthreads();

    int lane = tdx & 31, pg = tdx >> 5;
    float dts = g_dts;
    float lng = ln_g[lane], lnb = ln_b[lane];
    float b1r[4], w2r[4];
#pragma unroll
    for (int k4 = 0; k4 < 4; k4++) { b1r[k4] = b1[lane + 32 * k4]; w2r[k4] = w2[lane + 32 * k4]; }

    // phase 1: layernorm + MLP potential gradient
    for (int pp = 0; pp < 8; pp++) {
        int pos = pg * 8 + pp;
        float v = sXc[pos][lane];
        float s1 = v, s2 = v * v;
#pragma unroll
        for (int o = 16; o > 0; o >>= 1) {
            s1 += __shfl_xor_sync(0xffffffffu, s1, o);
            s2 += __shfl_xor_sync(0xffffffffu, s2, o);
        }
        float mu = s1 * (1.f / 32.f);
        float var = s2 * (1.f / 32.f) - mu * mu;
        float xin = (v - mu) * rsqrtf(var + 1e-5f) * lng + lnb;
        sXin[pos][lane] = xin;
        __syncwarp();
#pragma unroll
        for (int k4 = 0; k4 < 4; k4++) {
            int jj = lane + 32 * k4;
            float s = b1r[k4];
#pragma unroll
            for (int i = 0; i < 32; i++) s = fmaf(sXin[pos][i], sW1[i][jj], s);
            float sg = 1.f / (1.f + expf(-s));
            sCoef[pg * 128 + jj] = w2r[k4] * sg * (1.f + s * (1.f - sg));
        }
        __syncwarp();
        float gg = 0.f;
#pragma unroll 8
        for (int jj = 0; jj < 128; jj++) gg = fmaf(sW1[lane][jj], sCoef[pg * 128 + jj], gg);
        sG[pos][lane] = gg;
        __syncwarp();
    }
    __syncthreads();

    // phase 2: single pass over M/P rows k: Mg (lane j==k), M^T g, P^T P g
    float rMg[8], rMT[8], rU[8];
#pragma unroll
    for (int i = 0; i < 8; i++) { rMg[i] = 0.f; rMT[i] = 0.f; rU[i] = 0.f; }
    int j = lane;
    for (int k = 0; k < 32; k++) {
        for (int l = tdx; l < 1024; l += 256)
            sWc[l >> 5][l & 31] = JgW[(l >> 5) * 1024 + k * 32 + (l & 31)];
        __syncthreads();
        float bia = Jgb[k * 32 + j];
#pragma unroll
        for (int pp = 0; pp < 8; pp++) {
            int pos = pg * 8 + pp;
            float m = bia;
#pragma unroll
            for (int a = 0; a < 32; a++) m = fmaf(sXin[pos][a], sWc[a][j], m);
            float red = m * sG[pos][j];
#pragma unroll
            for (int o = 16; o > 0; o >>= 1) red += __shfl_xor_sync(0xffffffffu, red, o);
            if (j == k) rMg[pp] = red;
            rMT[pp] = fmaf(m, sG[pos][k], rMT[pp]);
        }
        __syncthreads();
        for (int l = tdx; l < 1024; l += 256)
            sWc[l >> 5][l & 31] = RgW[(l >> 5) * 1024 + k * 32 + (l & 31)];
        __syncthreads();
        float bib = Rgb[k * 32 + j];
#pragma unroll
        for (int pp = 0; pp < 8; pp++) {
            int pos = pg * 8 + pp;
            float p = bib;
#pragma unroll
            for (int a = 0; a < 32; a++) p = fmaf(sXin[pos][a], sWc[a][j], p);
            float q = p * sG[pos][j];
#pragma unroll
            for (int o = 16; o > 0; o >>= 1) q += __shfl_xor_sync(0xffffffffu, q, o);
            rU[pp] = fmaf(p, q, rU[pp]);
        }
        __syncthreads();
    }

    // finalize: out = xc + dt_scalar * (Mg - M^T g - P^T P g - 1e-4 g)
#pragma unroll
    for (int pp = 0; pp < 8; pp++) {
        int pos = pg * 8 + pp;
        float upd = rMg[pp] - rMT[pp] - rU[pp] - 1e-4f * sG[pos][j];
        sXin[pos][j] = sXc[pos][j] + dts * upd;
    }
    __syncthreads();
    for (int i = tdx; i < 2048; i += 256) {
        int d = i >> 6, w = i & 63;
        out[((f * Dz + d) * Hz + hh) * Wz + w] = sXin[w][d];
    }
}

// ---------------------------------------------------------------- launch
extern "C" void kernel_launch(void* const* d_in, const int* in_sizes, int n_in,
                              void* d_out, int out_size) {
    const float* x_real   = (const float*)d_in[0];
    const float* x_imag   = (const float*)d_in[1];
    const float* dt       = (const float*)d_in[2];
    const float* conv_w   = (const float*)d_in[3];
    const float* conv_b   = (const float*)d_in[4];
    const float* spec_re  = (const float*)d_in[5];
    const float* spec_im  = (const float*)d_in[6];
    const float* lam_re   = (const float*)d_in[7];
    const float* lam_im   = (const float*)d_in[8];
    const float* dt_param = (const float*)d_in[9];
    const float* sigma    = (const float*)d_in[10];
    const float* noise_r  = (const float*)d_in[11];
    const float* noise_i  = (const float*)d_in[12];
    const float* ln_g     = (const float*)d_in[13];
    const float* ln_b     = (const float*)d_in[14];
    const float* W1       = (const float*)d_in[15];
    const float* b1       = (const float*)d_in[16];
    const float* w2       = (const float*)d_in[17];
    // d_in[18] = b2 (constant in potential; zero gradient -> unused)
    const float* JgW      = (const float*)d_in[19];
    const float* Jgb      = (const float*)d_in[20];
    const float* RgW      = (const float*)d_in[21];
    const float* Rgb      = (const float*)d_in[22];
    float* out = (float*)d_out;

    k_prep<<<1, 32>>>(dt, lam_re, lam_im, dt_param, sigma);
    k_conv<<<512, 256>>>(x_real, x_imag, conv_w, conv_b);
    k_spectral<<<256, 256>>>(spec_re, spec_im);
    k_rfft2<<<512, 256>>>();
    k_scan<<<528, 256>>>();
    k_irfft2<<<512, 256>>>(noise_r, noise_i);
    k_ph<<<1024, 256>>>(ln_g, ln_b, W1, b1, w2, JgW, Jgb, RgW, Rgb, out);
}

// round 17
// speedup vs baseline: 1.0016x; 1.0001x over previous
#include <cuda_runtime.h>
#include <math.h>

// Problem constants
#define Bz 2
#define Tz 8
#define Cz 16
#define Hz 64
#define Wz 64
#define WFz 33
#define Dz 32
#define HIDz 128
#define HWz 4096
#define NIMG 256              // B*T*C
#define NIMG2 512             // 2B*T*C
#define UPLANE (Hz*WFz)       // 2112
#define USTR_T (Cz*UPLANE)    // 33792
#define NFIELD (Bz*Tz*Cz*HWz) // 1048576
#define NU (2*Bz*Tz*Cz*UPLANE)// 1081344

// Scratch (static __device__ — no allocation)
__device__ float g_xr[NFIELD];
__device__ float g_xi[NFIELD];
__device__ float g_ur[NU];
__device__ float g_ui[NU];
__device__ float g_Are[Cz], g_Aim[Cz];
__device__ float g_dts, g_nscale;

__device__ __forceinline__ float softplusf(float x) {
    return fmaxf(x, 0.f) + log1pf(expf(-fabsf(x)));
}

// ---------------------------------------------------------------- k_prep
__global__ void k_prep(const float* __restrict__ dt, const float* __restrict__ lam_re,
                       const float* __restrict__ lam_im, const float* __restrict__ dt_param,
                       const float* __restrict__ sigma) {
    int c = threadIdx.x;
    float dte = 0.f;
    if (c < Cz) {
        dte = dt[0] * softplusf(dt_param[c]);
        float are = -softplusf(lam_re[c]) * dte;
        float aim = lam_im[c] * dte;
        float m = expf(are);
        g_Are[c] = m * cosf(aim);
        g_Aim[c] = m * sinf(aim);
    }
    float s = dte;
#pragma unroll
    for (int o = 16; o > 0; o >>= 1) s += __shfl_xor_sync(0xffffffffu, s, o);
    if (c == 0) {
        float dts = s / 16.f;
        g_dts = dts;
        g_nscale = sigma[0] * sqrtf(dts);
    }
}

// ---------------------------------------------------------------- k_conv
// x1 = x + conv3x3(x) + b, applied to real and imag parts.
// block: (frame 0..15, part 0..1, cout 0..15) -> 512 blocks, 256 threads
__global__ void k_conv(const float* __restrict__ xr, const float* __restrict__ xi,
                       const float* __restrict__ conv_w, const float* __restrict__ conv_b) {
    __shared__ float sp[66][66];
    int bidx = blockIdx.x;
    int co   = bidx & 15;
    int part = (bidx >> 4) & 1;
    int f    = bidx >> 5;
    const float* src = part ? xi : xr;
    float*       dst = part ? g_xi : g_xr;
    int t = threadIdx.x;

    for (int i = t; i < 66 * 66; i += 256) ((float*)sp)[i] = 0.f;
    __syncthreads();

    float acc[16];
#pragma unroll
    for (int i = 0; i < 16; i++) acc[i] = 0.f;

    for (int ci = 0; ci < Cz; ci++) {
        const float* p = src + (f * Cz + ci) * HWz;
        for (int idx = t; idx < HWz; idx += 256)
            sp[(idx >> 6) + 1][(idx & 63) + 1] = p[idx];
        __syncthreads();
        const float* w = conv_w + (co * Cz + ci) * 9;
        float w0 = w[0], w1 = w[1], w2 = w[2], w3 = w[3], w4 = w[4],
              w5 = w[5], w6 = w[6], w7 = w[7], w8 = w[8];
#pragma unroll
        for (int i = 0; i < 16; i++) {
            int idx = t + 256 * i;
            int y = (idx >> 6) + 1, x = (idx & 63) + 1;
            float a = acc[i];
            a = fmaf(w0, sp[y - 1][x - 1], a);
            a = fmaf(w1, sp[y - 1][x    ], a);
            a = fmaf(w2, sp[y - 1][x + 1], a);
            a = fmaf(w3, sp[y    ][x - 1], a);
            a = fmaf(w4, sp[y    ][x    ], a);
            a = fmaf(w5, sp[y    ][x + 1], a);
            a = fmaf(w6, sp[y + 1][x - 1], a);
            a = fmaf(w7, sp[y + 1][x    ], a);
            a = fmaf(w8, sp[y + 1][x + 1], a);
            acc[i] = a;
        }
        __syncthreads();
    }
    const float* me = src + (f * Cz + co) * HWz;
    float*       de = dst + (f * Cz + co) * HWz;
    float bb = conv_b[co];
#pragma unroll
    for (int i = 0; i < 16; i++) {
        int idx = t + 256 * i;
        de[idx] = me[idx] + acc[i] + bb;
    }
}

// ---------------------------------------------------------------- DFT passes
// 64-pt DFT along H (columns) and W (rows), in-place via register double-buffer.
// sgn = -1 forward (e^{-i}), +1 inverse (e^{+i}); each pass scales by 1/8 (ortho).
__device__ void dft_h(float (*ar)[65], float (*ai)[65],
                      const float* __restrict__ tc, const float* __restrict__ ts, float sgn) {
    int t = threadIdx.x;
    int cx = t & 63, kb = t >> 6;
    float orr[16], ori[16];
#pragma unroll
    for (int i = 0; i < 16; i++) { orr[i] = 0.f; ori[i] = 0.f; }
    for (int r = 0; r < 64; r++) {
        float x = ar[r][cx], y = ai[r][cx];
        float xs = sgn * x, ym = -sgn * y;
        int m = (kb * r) & 63, st = (r << 2) & 63;
#pragma unroll
        for (int i = 0; i < 16; i++) {
            float c = tc[m], s = ts[m];
            orr[i] = fmaf(x, c, fmaf(ym, s, orr[i]));
            ori[i] = fmaf(y, c, fmaf(xs, s, ori[i]));
            m = (m + st) & 63;
        }
    }
    __syncthreads();
#pragma unroll
    for (int i = 0; i < 16; i++) {
        int k = kb + 4 * i;
        ar[k][cx] = orr[i] * 0.125f;
        ai[k][cx] = ori[i] * 0.125f;
    }
    __syncthreads();
}

__device__ void dft_w(float (*ar)[65], float (*ai)[65],
                      const float* __restrict__ tc, const float* __restrict__ ts, float sgn) {
    int t = threadIdx.x;
    int r = t & 63, kb = t >> 6;
    float orr[16], ori[16];
#pragma unroll
    for (int i = 0; i < 16; i++) { orr[i] = 0.f; ori[i] = 0.f; }
    for (int n = 0; n < 64; n++) {
        float x = ar[r][n], y = ai[r][n];
        float xs = sgn * x, ym = -sgn * y;
        int m = (kb * n) & 63, st = (n << 2) & 63;
#pragma unroll
        for (int i = 0; i < 16; i++) {
            float c = tc[m], s = ts[m];
            orr[i] = fmaf(x, c, fmaf(ym, s, orr[i]));
            ori[i] = fmaf(y, c, fmaf(xs, s, ori[i]));
            m = (m + st) & 63;
        }
    }
    __syncthreads();
#pragma unroll
    for (int i = 0; i < 16; i++) {
        int k = kb + 4 * i;
        ar[r][k] = orr[i] * 0.125f;
        ai[r][k] = ori[i] * 0.125f;
    }
    __syncthreads();
}

#define FFT_SHARED                                                        \
    __shared__ float sar[64][65];                                         \
    __shared__ float sai[64][65];                                         \
    __shared__ float stc[64], sts[64];                                    \
    {                                                                     \
        int t_ = threadIdx.x;                                             \
        if (t_ < 64) {                                                    \
            float th = 0.09817477042468103f * (float)t_;                  \
            stc[t_] = cosf(th);                                           \
            sts[t_] = sinf(th);                                           \
        }                                                                 \
    }

// ---------------------------------------------------------------- k_spectral
// x += ifft2( fft2(x) * filt ), per (b,t,c) image. 256 blocks.
__global__ void k_spectral(const float* __restrict__ spec_re, const float* __restrict__ spec_im) {
    FFT_SHARED
    int img = blockIdx.x;
    int c = img & 15;
    int base = img * HWz;
    int t = threadIdx.x;
    for (int idx = t; idx < HWz; idx += 256) {
        int hh = idx >> 6, ww = idx & 63;
        sar[hh][ww] = g_xr[base + idx];
        sai[hh][ww] = g_xi[base + idx];
    }
    __syncthreads();
    dft_h(sar, sai, stc, sts, -1.f);
    dft_w(sar, sai, stc, sts, -1.f);
    for (int idx = t; idx < HWz; idx += 256) {
        int hh = idx >> 6, ww = idx & 63;
        float fr = spec_re[c * HWz + idx], fi = spec_im[c * HWz + idx];
        float x = sar[hh][ww], y = sai[hh][ww];
        sar[hh][ww] = x * fr - y * fi;
        sai[hh][ww] = x * fi + y * fr;
    }
    __syncthreads();
    dft_h(sar, sai, stc, sts, 1.f);
    dft_w(sar, sai, stc, sts, 1.f);
    for (int idx = t; idx < HWz; idx += 256) {
        int hh = idx >> 6, ww = idx & 63;
        g_xr[base + idx] += sar[hh][ww];
        g_xi[base + idx] += sai[hh][ww];
    }
}

// ---------------------------------------------------------------- k_rfft2
// u = rfft2(xs) for xs = [x.real ; x.imag] (bb = 0..3). 512 blocks.
__global__ void k_rfft2() {
    FFT_SHARED
    int img = blockIdx.x;
    int bb = img / (Tz * Cz);
    int rem = img % (Tz * Cz);
    const float* src = (bb < 2) ? g_xr : g_xi;
    int base = ((bb & 1) * Tz * Cz + rem) * HWz;
    int t = threadIdx.x;
    for (int idx = t; idx < HWz; idx += 256) {
        int hh = idx >> 6, ww = idx & 63;
        sar[hh][ww] = src[base + idx];
        sai[hh][ww] = 0.f;
    }
    __syncthreads();
    dft_h(sar, sai, stc, sts, -1.f);
    dft_w(sar, sai, stc, sts, -1.f);
    int ub = img * UPLANE;
    for (int idx = t; idx < UPLANE; idx += 256) {
        int hh = idx / 33, ww = idx % 33;
        g_ur[ub + idx] = sar[hh][ww];
        g_ui[ub + idx] = sai[hh][ww];
    }
}

// ---------------------------------------------------------------- k_scan
// h_t = A[c] h_{t-1} + u_t  (in-place over u), per frequency bin.
__global__ void k_scan() {
    int idx = blockIdx.x * blockDim.x + threadIdx.x;
    if (idx >= 4 * USTR_T) return;
    int bb = idx / USTR_T;
    int inner = idx % USTR_T;
    int c = inner / UPLANE;
    float Ar = g_Are[c], Ai = g_Aim[c];
    int base = bb * (Tz * USTR_T) + inner;
    float hr = 0.f, hi = 0.f;
#pragma unroll
    for (int tt = 0; tt < Tz; tt++) {
        int o = base + tt * USTR_T;
        float ur = g_ur[o], ui = g_ui[o];
        float nr = Ar * hr - Ai * hi + ur;
        float ni = Ar * hi + Ai * hr + ui;
        hr = nr; hi = ni;
        g_ur[o] = hr; g_ui[o] = hi;
    }
}

// ---------------------------------------------------------------- k_irfft2
// x += irfft2(h) + noise*scale.  Hermitian-extend half spectrum, ifft2, Re part.
__global__ void k_irfft2(const float* __restrict__ noise_r, const float* __restrict__ noise_i) {
    FFT_SHARED
    int img = blockIdx.x;
    int bb = img / (Tz * Cz);
    int rem = img % (Tz * Cz);
    int ub = img * UPLANE;
    int t = threadIdx.x;
    for (int idx = t; idx < HWz; idx += 256) {
        int hh = idx >> 6, ww = idx & 63;
        float re, im;
        if (ww < WFz) {
            re = g_ur[ub + hh * 33 + ww];
            im = g_ui[ub + hh * 33 + ww];
        } else {
            int hs = (64 - hh) & 63;
            int ws = 64 - ww;
            re =  g_ur[ub + hs * 33 + ws];
            im = -g_ui[ub + hs * 33 + ws];
        }
        sar[hh][ww] = re;
        sai[hh][ww] = im;
    }
    __syncthreads();
    dft_h(sar, sai, stc, sts, 1.f);
    dft_w(sar, sai, stc, sts, 1.f);
    float ns = g_nscale;
    int base = ((bb & 1) * Tz * Cz + rem) * HWz;
    float* dst = (bb < 2) ? g_xr : g_xi;
    const float* nz = (bb < 2) ? noise_r : noise_i;
    for (int idx = t; idx < HWz; idx += 256) {
        int hh = idx >> 6, ww = idx & 63;
        dst[base + idx] += sar[hh][ww] + ns * nz[base + idx];
    }
}

// ---------------------------------------------------------------- k_ph
// Port-Hamiltonian layer. Block = one (b,t,h) row of 64 positions. 1024 blocks.
__global__ void __launch_bounds__(256) k_ph(
    const float* __restrict__ ln_g, const float* __restrict__ ln_b,
    const float* __restrict__ W1, const float* __restrict__ b1,
    const float* __restrict__ w2,
    const float* __restrict__ JgW, const float* __restrict__ Jgb,
    const float* __restrict__ RgW, const float* __restrict__ Rgb,
    float* __restrict__ out) {
    __shared__ float sW1[32][129];
    __shared__ float sXc[64][33];
    __shared__ float sXin[64][33];
    __shared__ float sG[64][33];
    __shared__ float sWc[32][33];           // also aliased as coef buffer in phase 1
    float* sCoef = &sWc[0][0];              // 1056 floats >= 8*128

    int tdx = threadIdx.x;
    int bid = blockIdx.x;
    int f = bid >> 6;       // frame b*T+t
    int hh = bid & 63;

    for (int i = tdx; i < 32 * 128; i += 256) sW1[i >> 7][i & 127] = W1[i];
    for (int i = tdx; i < 1024; i += 256) {
        int c = i >> 6, w = i & 63;
        int gi = (f * Cz + c) * HWz + hh * 64 + w;
        sXc[w][c] = g_xr[gi];
        sXc[w][16 + c] = g_xi[gi];
    }
    __syncthreads();

    int lane = tdx & 31, pg = tdx >> 5;
    float dts = g_dts;
    float lng = ln_g[lane], lnb = ln_b[lane];
    float b1r[4], w2r[4];
#pragma unroll
    for (int k4 = 0; k4 < 4; k4++) { b1r[k4] = b1[lane + 32 * k4]; w2r[k4] = w2[lane + 32 * k4]; }

    // phase 1: layernorm + MLP potential gradient
    for (int pp = 0; pp < 8; pp++) {
        int pos = pg * 8 + pp;
        float v = sXc[pos][lane];
        float s1 = v, s2 = v * v;
#pragma unroll
        for (int o = 16; o > 0; o >>= 1) {
            s1 += __shfl_xor_sync(0xffffffffu, s1, o);
            s2 += __shfl_xor_sync(0xffffffffu, s2, o);
        }
        float mu = s1 * (1.f / 32.f);
        float var = s2 * (1.f / 32.f) - mu * mu;
        float xin = (v - mu) * rsqrtf(var + 1e-5f) * lng + lnb;
        sXin[pos][lane] = xin;
        __syncwarp();
#pragma unroll
        for (int k4 = 0; k4 < 4; k4++) {
            int jj = lane + 32 * k4;
            float s = b1r[k4];
#pragma unroll
            for (int i = 0; i < 32; i++) s = fmaf(sXin[pos][i], sW1[i][jj], s);
            float sg = 1.f / (1.f + expf(-s));
            sCoef[pg * 128 + jj] = w2r[k4] * sg * (1.f + s * (1.f - sg));
        }
        __syncwarp();
        float gg = 0.f;
#pragma unroll 8
        for (int jj = 0; jj < 128; jj++) gg = fmaf(sW1[lane][jj], sCoef[pg * 128 + jj], gg);
        sG[pos][lane] = gg;
        __syncwarp();
    }
    __syncthreads();

    // phase 2: single pass over M/P rows k: Mg (lane j==k), M^T g, P^T P g
    float rMg[8], rMT[8], rU[8];
#pragma unroll
    for (int i = 0; i < 8; i++) { rMg[i] = 0.f; rMT[i] = 0.f; rU[i] = 0.f; }
    int j = lane;
    for (int k = 0; k < 32; k++) {
        for (int l = tdx; l < 1024; l += 256)
            sWc[l >> 5][l & 31] = JgW[(l >> 5) * 1024 + k * 32 + (l & 31)];
        __syncthreads();
        float bia = Jgb[k * 32 + j];
#pragma unroll
        for (int pp = 0; pp < 8; pp++) {
            int pos = pg * 8 + pp;
            float m = bia;
#pragma unroll
            for (int a = 0; a < 32; a++) m = fmaf(sXin[pos][a], sWc[a][j], m);
            float red = m * sG[pos][j];
#pragma unroll
            for (int o = 16; o > 0; o >>= 1) red += __shfl_xor_sync(0xffffffffu, red, o);
            if (j == k) rMg[pp] = red;
            rMT[pp] = fmaf(m, sG[pos][k], rMT[pp]);
        }
        __syncthreads();
        for (int l = tdx; l < 1024; l += 256)
            sWc[l >> 5][l & 31] = RgW[(l >> 5) * 1024 + k * 32 + (l & 31)];
        __syncthreads();
        float bib = Rgb[k * 32 + j];
#pragma unroll
        for (int pp = 0; pp < 8; pp++) {
            int pos = pg * 8 + pp;
            float p = bib;
#pragma unroll
            for (int a = 0; a < 32; a++) p = fmaf(sXin[pos][a], sWc[a][j], p);
            float q = p * sG[pos][j];
#pragma unroll
            for (int o = 16; o > 0; o >>= 1) q += __shfl_xor_sync(0xffffffffu, q, o);
            rU[pp] = fmaf(p, q, rU[pp]);
        }
        __syncthreads();
    }

    // finalize: out = xc + dt_scalar * (Mg - M^T g - P^T P g - 1e-4 g)
#pragma unroll
    for (int pp = 0; pp < 8; pp++) {
        int pos = pg * 8 + pp;
        float upd = rMg[pp] - rMT[pp] - rU[pp] - 1e-4f * sG[pos][j];
        sXin[pos][j] = sXc[pos][j] + dts * upd;
    }
    __syncthreads();
    for (int i = tdx; i < 2048; i += 256) {
        int d = i >> 6, w = i & 63;
        out[((f * Dz + d) * Hz + hh) * Wz + w] = sXin[w][d];
    }
}

// ---------------------------------------------------------------- launch
extern "C" void kernel_launch(void* const* d_in, const int* in_sizes, int n_in,
                              void* d_out, int out_size) {
    const float* x_real   = (const float*)d_in[0];
    const float* x_imag   = (const float*)d_in[1];
    const float* dt       = (const float*)d_in[2];
    const float* conv_w   = (const float*)d_in[3];
    const float* conv_b   = (const float*)d_in[4];
    const float* spec_re  = (const float*)d_in[5];
    const float* spec_im  = (const float*)d_in[6];
    const float* lam_re   = (const float*)d_in[7];
    const float* lam_im   = (const float*)d_in[8];
    const float* dt_param = (const float*)d_in[9];
    const float* sigma    = (const float*)d_in[10];
    const float* noise_r  = (const float*)d_in[11];
    const float* noise_i  = (const float*)d_in[12];
    const float* ln_g     = (const float*)d_in[13];
    const float* ln_b     = (const float*)d_in[14];
    const float* W1       = (const float*)d_in[15];
    const float* b1       = (const float*)d_in[16];
    const float* w2       = (const float*)d_in[17];
    // d_in[18] = b2 (constant in potential; zero gradient -> unused)
    const float* JgW      = (const float*)d_in[19];
    const float* Jgb      = (const float*)d_in[20];
    const float* RgW      = (const float*)d_in[21];
    const float* Rgb      = (const float*)d_in[22];
    float* out = (float*)d_out;

    k_prep<<<1, 32>>>(dt, lam_re, lam_im, dt_param, sigma);
    k_conv<<<512, 256>>>(x_real, x_imag, conv_w, conv_b);
    k_spectral<<<256, 256>>>(spec_re, spec_im);
    k_rfft2<<<512, 256>>>();
    k_scan<<<528, 256>>>();
    k_irfft2<<<512, 256>>>(noise_r, noise_i);
    k_ph<<<1024, 256>>>(ln_g, ln_b, W1, b1, w2, JgW, Jgb, RgW, Rgb, out);
}